// round 1
// baseline (speedup 1.0000x reference)
#include <cuda_runtime.h>

#define SEQ 2048
#define EMB 512
#define NH 8
#define DK 64
#define NB 4
#define NEGV -1000000000.0f

// Scratch (allocation-free rule: __device__ globals)
__device__ float g_q[(size_t)NB*NH*SEQ*DK];
__device__ float g_k[(size_t)NB*NH*SEQ*DK];
__device__ float g_v[(size_t)NB*NH*SEQ*DK];
__device__ float g_att[(size_t)NB*NH*SEQ*DK];

// ---------------------------------------------------------------------------
// Generic projection GEMM: C[m][n] = sum_k X[m][k]*W[n][k] + bias[n]
// M=8192, N=512, K=512. 64x64 tile, BK=16, 256 threads, 4x4 micro-tile.
// headLayout=1: store to [(b*8+h)*2048+s]*64+d  (b=m>>11, s=m&2047, h=n>>6, d=n&63)
// headLayout=0: store to m*512+n
// ---------------------------------------------------------------------------
__global__ __launch_bounds__(256) void proj_kernel(
    const float* __restrict__ X, const float* __restrict__ W,
    const float* __restrict__ bias, float* __restrict__ out, int headLayout)
{
    __shared__ float As[16][68];
    __shared__ float Bs[16][68];

    const int t  = threadIdx.x;
    const int tx = t & 15, ty = t >> 4;
    const int m0 = blockIdx.y * 64;
    const int n0 = blockIdx.x * 64;

    const int lrow = t >> 2;        // 0..63
    const int lk4  = (t & 3) * 4;   // 0,4,8,12

    float acc[4][4] = {};

    for (int k0 = 0; k0 < EMB; k0 += 16) {
        float4 a = *(const float4*)&X[(size_t)(m0 + lrow) * EMB + k0 + lk4];
        float4 b = *(const float4*)&W[(size_t)(n0 + lrow) * EMB + k0 + lk4];
        __syncthreads();
        As[lk4 + 0][lrow] = a.x; As[lk4 + 1][lrow] = a.y;
        As[lk4 + 2][lrow] = a.z; As[lk4 + 3][lrow] = a.w;
        Bs[lk4 + 0][lrow] = b.x; Bs[lk4 + 1][lrow] = b.y;
        Bs[lk4 + 2][lrow] = b.z; Bs[lk4 + 3][lrow] = b.w;
        __syncthreads();
        #pragma unroll
        for (int kk = 0; kk < 16; kk++) {
            float ar[4], br[4];
            #pragma unroll
            for (int i = 0; i < 4; i++) ar[i] = As[kk][ty + 16 * i];
            #pragma unroll
            for (int j = 0; j < 4; j++) br[j] = Bs[kk][tx + 16 * j];
            #pragma unroll
            for (int i = 0; i < 4; i++)
                #pragma unroll
                for (int j = 0; j < 4; j++)
                    acc[i][j] += ar[i] * br[j];
        }
    }

    #pragma unroll
    for (int i = 0; i < 4; i++) {
        const int m = m0 + ty + 16 * i;
        #pragma unroll
        for (int j = 0; j < 4; j++) {
            const int n = n0 + tx + 16 * j;
            const float c = acc[i][j] + bias[n];
            if (headLayout) {
                const int bb = m >> 11, s = m & 2047, h = n >> 6, d = n & 63;
                out[((size_t)((bb << 3) + h) * SEQ + s) * DK + d] = c;
            } else {
                out[(size_t)m * EMB + n] = c;
            }
        }
    }
}

// ---------------------------------------------------------------------------
// Flash-style attention over one (b,h) and a 64-query tile.
// scores = (Q K^T) * 8.0, masked to -1e9 where mask==0, online softmax, P@V.
// 256 threads as 16x16 grid, each owning a 4x4 register micro-tile.
// ---------------------------------------------------------------------------
__global__ __launch_bounds__(256) void attn_kernel(
    const float* __restrict__ Q, const float* __restrict__ K,
    const float* __restrict__ V, const int* __restrict__ mask,
    float* __restrict__ O)
{
    extern __shared__ float sm[];
    float* Qs = sm;               // 64 x 64 (row-major)
    float* Ks = Qs + 64 * 64;     // 64 x 64, XOR-swizzled at float4 granularity
    float* Vs = Ks + 64 * 64;     // 64 x 64 (row-major)
    float* Ps = Vs + 64 * 64;     // 64 x 64 (row-major)

    const int t  = threadIdx.x;
    const int tx = t & 15, ty = t >> 4;
    const int bh = blockIdx.y;
    const int b  = bh >> 3;
    const int q0 = blockIdx.x * 64;

    const float* qp = Q + (size_t)bh * SEQ * DK;
    const float* kp = K + (size_t)bh * SEQ * DK;
    const float* vp = V + (size_t)bh * SEQ * DK;
    const int*   mp = mask + (size_t)b * SEQ * SEQ;

    const int lrow = t >> 2;        // 0..63
    const int lc   = (t & 3) * 16;  // 0,16,32,48

    // Load Q tile once
    #pragma unroll
    for (int i = 0; i < 16; i += 4) {
        float4 x = *(const float4*)&qp[(size_t)(q0 + lrow) * DK + lc + i];
        *(float4*)&Qs[lrow * 64 + lc + i] = x;
    }

    float m_[4], l_[4], o_[4][4];
    #pragma unroll
    for (int i = 0; i < 4; i++) {
        m_[i] = -1e30f; l_[i] = 0.0f;
        #pragma unroll
        for (int j = 0; j < 4; j++) o_[i][j] = 0.0f;
    }

    for (int k0 = 0; k0 < SEQ; k0 += 64) {
        __syncthreads();   // previous phase-C reads of Ks/Vs/Ps done
        // Load K (swizzled) and V tiles
        #pragma unroll
        for (int i = 0; i < 16; i += 4) {
            const int c = lc + i;
            float4 kv = *(const float4*)&kp[(size_t)(k0 + lrow) * DK + c];
            const int c4 = c >> 2;
            *(float4*)&Ks[lrow * 64 + ((c4 ^ (lrow & 15)) << 2)] = kv;
            float4 vv = *(const float4*)&vp[(size_t)(k0 + lrow) * DK + c];
            *(float4*)&Vs[lrow * 64 + c] = vv;
        }
        __syncthreads();

        // Phase A: S = Q K^T (64x64x64)
        float sacc[4][4] = {};
        #pragma unroll
        for (int d4 = 0; d4 < 16; d4++) {
            float qr[4][4], kr[4][4];
            #pragma unroll
            for (int i = 0; i < 4; i++)
                *(float4*)qr[i] = *(const float4*)&Qs[(ty + 16 * i) * 64 + (d4 << 2)];
            #pragma unroll
            for (int j = 0; j < 4; j++) {
                const int r = tx + 16 * j;
                *(float4*)kr[j] = *(const float4*)&Ks[r * 64 + ((d4 ^ (r & 15)) << 2)];
            }
            #pragma unroll
            for (int e = 0; e < 4; e++)
                #pragma unroll
                for (int i = 0; i < 4; i++)
                    #pragma unroll
                    for (int j = 0; j < 4; j++)
                        sacc[i][j] += qr[i][e] * kr[j][e];
        }

        // Scale (*8, faithful quirk) + mask
        #pragma unroll
        for (int i = 0; i < 4; i++) {
            const int mrow = q0 + ty + 16 * i;
            #pragma unroll
            for (int j = 0; j < 4; j++) {
                const int mcol = k0 + tx + 16 * j;
                const int mv = mp[(size_t)mrow * SEQ + mcol];
                sacc[i][j] = mv ? sacc[i][j] * 8.0f : NEGV;
            }
        }

        // Online softmax update, row r = ty + 16*i spans 16 lanes (same ty)
        #pragma unroll
        for (int i = 0; i < 4; i++) {
            float mt = fmaxf(fmaxf(sacc[i][0], sacc[i][1]),
                             fmaxf(sacc[i][2], sacc[i][3]));
            #pragma unroll
            for (int off = 1; off < 16; off <<= 1)
                mt = fmaxf(mt, __shfl_xor_sync(0xffffffffu, mt, off));
            const float mnew  = fmaxf(m_[i], mt);
            const float scale = __expf(m_[i] - mnew);
            float rs = 0.0f;
            #pragma unroll
            for (int j = 0; j < 4; j++) {
                sacc[i][j] = __expf(sacc[i][j] - mnew);
                rs += sacc[i][j];
            }
            #pragma unroll
            for (int off = 1; off < 16; off <<= 1)
                rs += __shfl_xor_sync(0xffffffffu, rs, off);
            l_[i] = l_[i] * scale + rs;
            m_[i] = mnew;
            #pragma unroll
            for (int j = 0; j < 4; j++) o_[i][j] *= scale;
        }

        // Write P tile
        #pragma unroll
        for (int i = 0; i < 4; i++)
            #pragma unroll
            for (int j = 0; j < 4; j++)
                Ps[(ty + 16 * i) * 64 + tx + 16 * j] = sacc[i][j];
        __syncthreads();

        // Phase C: O += P @ V (64x64x64)
        #pragma unroll
        for (int k4 = 0; k4 < 16; k4++) {
            float pr[4][4];
            #pragma unroll
            for (int i = 0; i < 4; i++)
                *(float4*)pr[i] = *(const float4*)&Ps[(ty + 16 * i) * 64 + (k4 << 2)];
            #pragma unroll
            for (int e = 0; e < 4; e++) {
                float vr[4];
                #pragma unroll
                for (int j = 0; j < 4; j++)
                    vr[j] = Vs[((k4 << 2) + e) * 64 + tx + 16 * j];
                #pragma unroll
                for (int i = 0; i < 4; i++)
                    #pragma unroll
                    for (int j = 0; j < 4; j++)
                        o_[i][j] += pr[i][e] * vr[j];
            }
        }
    }

    // Epilogue: normalize and store [bh][s][d] (contiguous == "no-transpose" quirk)
    float* op = O + (size_t)bh * SEQ * DK;
    #pragma unroll
    for (int i = 0; i < 4; i++) {
        const float inv = 1.0f / l_[i];
        #pragma unroll
        for (int j = 0; j < 4; j++)
            op[(size_t)(q0 + ty + 16 * i) * DK + tx + 16 * j] = o_[i][j] * inv;
    }
}

extern "C" void kernel_launch(void* const* d_in, const int* in_sizes, int n_in,
                              void* d_out, int out_size)
{
    (void)in_sizes; (void)n_in; (void)out_size;
    const float* query  = (const float*)d_in[0];
    const float* key_in = (const float*)d_in[1];
    const float* value  = (const float*)d_in[2];
    const int*   mask   = (const int*)  d_in[3];
    const float* Wq = (const float*)d_in[4];
    const float* bq = (const float*)d_in[5];
    const float* Wk = (const float*)d_in[6];
    const float* bk = (const float*)d_in[7];
    const float* Wv = (const float*)d_in[8];
    const float* bv = (const float*)d_in[9];
    const float* Wo = (const float*)d_in[10];
    const float* bo = (const float*)d_in[11];
    float* out = (float*)d_out;

    float *qb, *kb, *vb, *ab;
    cudaGetSymbolAddress((void**)&qb, g_q);
    cudaGetSymbolAddress((void**)&kb, g_k);
    cudaGetSymbolAddress((void**)&vb, g_v);
    cudaGetSymbolAddress((void**)&ab, g_att);

    const int attn_smem = 4 * 64 * 64 * (int)sizeof(float);  // 64 KB
    cudaFuncSetAttribute(attn_kernel,
                         cudaFuncAttributeMaxDynamicSharedMemorySize, attn_smem);

    dim3 pg(EMB / 64, (NB * SEQ) / 64);   // (8, 128)
    proj_kernel<<<pg, 256>>>(query,  Wq, bq, qb, 1);
    proj_kernel<<<pg, 256>>>(key_in, Wk, bk, kb, 1);
    proj_kernel<<<pg, 256>>>(value,  Wv, bv, vb, 1);

    dim3 ag(SEQ / 64, NB * NH);           // (32, 32)
    attn_kernel<<<ag, 256, attn_smem>>>(qb, kb, vb, mask, ab);

    proj_kernel<<<pg, 256>>>(ab, Wo, bo, out, 0);
}

// round 2
// speedup vs baseline: 1.1585x; 1.1585x over previous
#include <cuda_runtime.h>

#define SEQ 2048
#define EMB 512
#define NH 8
#define DK 64
#define NB 4
#define NEGV -1000000000.0f

// Scratch (allocation-free rule: __device__ globals)
__device__ float g_q[(size_t)NB*NH*SEQ*DK];
__device__ float g_k[(size_t)NB*NH*SEQ*DK];
__device__ float g_v[(size_t)NB*NH*SEQ*DK];
__device__ float g_att[(size_t)NB*NH*SEQ*DK];

// ---------------------------------------------------------------------------
// Packed fp32x2 math (sm_103a): 2 FMAs per issue slot.
// ---------------------------------------------------------------------------
union F2U { float2 f; unsigned long long u; };

__device__ __forceinline__ float2 ffma2(float2 a, float2 b, float2 c) {
    F2U A, B, C, D; A.f = a; B.f = b; C.f = c;
    asm("fma.rn.f32x2 %0, %1, %2, %3;" : "=l"(D.u) : "l"(A.u), "l"(B.u), "l"(C.u));
    return D.f;
}
__device__ __forceinline__ float2 fmul2(float2 a, float2 b) {
    F2U A, B, D; A.f = a; B.f = b;
    asm("mul.rn.f32x2 %0, %1, %2;" : "=l"(D.u) : "l"(A.u), "l"(B.u));
    return D.f;
}

// ---------------------------------------------------------------------------
// Projection GEMM: C[m][n] = sum_k X[m][k]*W[n][k] + bias[n]
// M=8192, N=512, K=512. 128x128 tile, BK=16, 256 threads, 8x8 micro-tile
// with packed f32x2 accumulation (2 FLOP/smem-byte -> fma-bound).
// headLayout=1: store to [(b*8+h)*2048+s]*64+d
// ---------------------------------------------------------------------------
__global__ __launch_bounds__(256, 2) void proj_kernel(
    const float* __restrict__ X, const float* __restrict__ W,
    const float* __restrict__ bias, float* __restrict__ out, int headLayout)
{
    __shared__ float As[16][132];   // As[k][m]
    __shared__ float Bs[16][132];   // Bs[k][n]

    const int t  = threadIdx.x;
    const int tx = t & 15, ty = t >> 4;
    const int m0 = blockIdx.y * 128;
    const int n0 = blockIdx.x * 128;

    const int lrow = t >> 1;         // 0..127
    const int lk   = (t & 1) * 8;    // 0 or 8

    float2 acc[8][2][2];
    #pragma unroll
    for (int i = 0; i < 8; i++)
        #pragma unroll
        for (int g = 0; g < 2; g++) {
            acc[i][g][0] = make_float2(0.f, 0.f);
            acc[i][g][1] = make_float2(0.f, 0.f);
        }

    for (int k0 = 0; k0 < EMB; k0 += 16) {
        float4 a0 = *(const float4*)&X[(size_t)(m0 + lrow) * EMB + k0 + lk];
        float4 a1 = *(const float4*)&X[(size_t)(m0 + lrow) * EMB + k0 + lk + 4];
        float4 b0 = *(const float4*)&W[(size_t)(n0 + lrow) * EMB + k0 + lk];
        float4 b1 = *(const float4*)&W[(size_t)(n0 + lrow) * EMB + k0 + lk + 4];
        __syncthreads();
        As[lk + 0][lrow] = a0.x; As[lk + 1][lrow] = a0.y;
        As[lk + 2][lrow] = a0.z; As[lk + 3][lrow] = a0.w;
        As[lk + 4][lrow] = a1.x; As[lk + 5][lrow] = a1.y;
        As[lk + 6][lrow] = a1.z; As[lk + 7][lrow] = a1.w;
        Bs[lk + 0][lrow] = b0.x; Bs[lk + 1][lrow] = b0.y;
        Bs[lk + 2][lrow] = b0.z; Bs[lk + 3][lrow] = b0.w;
        Bs[lk + 4][lrow] = b1.x; Bs[lk + 5][lrow] = b1.y;
        Bs[lk + 6][lrow] = b1.z; Bs[lk + 7][lrow] = b1.w;
        __syncthreads();
        #pragma unroll
        for (int kk = 0; kk < 16; kk++) {
            float4 bv0 = *(const float4*)&Bs[kk][4 * tx];
            float4 bv1 = *(const float4*)&Bs[kk][64 + 4 * tx];
            float2 b00 = make_float2(bv0.x, bv0.y);
            float2 b01 = make_float2(bv0.z, bv0.w);
            float2 b10 = make_float2(bv1.x, bv1.y);
            float2 b11 = make_float2(bv1.z, bv1.w);
            #pragma unroll
            for (int i = 0; i < 8; i++) {
                const float av = As[kk][ty + 16 * i];
                const float2 aa = make_float2(av, av);
                acc[i][0][0] = ffma2(aa, b00, acc[i][0][0]);
                acc[i][0][1] = ffma2(aa, b01, acc[i][0][1]);
                acc[i][1][0] = ffma2(aa, b10, acc[i][1][0]);
                acc[i][1][1] = ffma2(aa, b11, acc[i][1][1]);
            }
        }
    }

    #pragma unroll
    for (int g = 0; g < 2; g++) {
        const int n = n0 + 64 * g + 4 * tx;
        const float4 bb = *(const float4*)&bias[n];
        #pragma unroll
        for (int i = 0; i < 8; i++) {
            const int m = m0 + ty + 16 * i;
            float4 c;
            c.x = acc[i][g][0].x + bb.x;
            c.y = acc[i][g][0].y + bb.y;
            c.z = acc[i][g][1].x + bb.z;
            c.w = acc[i][g][1].y + bb.w;
            if (headLayout) {
                const int bb_ = m >> 11, s = m & 2047, h = n >> 6, d = n & 63;
                *(float4*)&out[((size_t)((bb_ << 3) + h) * SEQ + s) * DK + d] = c;
            } else {
                *(float4*)&out[(size_t)m * EMB + n] = c;
            }
        }
    }
}

// ---------------------------------------------------------------------------
// Flash-style attention: one (b,h), 128-query tile, 64-key inner tiles.
// 256 threads, 8x4 micro-tile, packed f32x2. K stored transposed in smem so
// the key dimension is contiguous for packed pairs.
// ---------------------------------------------------------------------------
__global__ __launch_bounds__(256, 2) void attn_kernel(
    const float* __restrict__ Q, const float* __restrict__ K,
    const float* __restrict__ V, const int* __restrict__ mask,
    float* __restrict__ O)
{
    extern __shared__ float sm[];
    float* Qs = sm;              // 128 x 68  (row=query, col=dim)
    float* Kt = Qs + 128 * 68;   // 64 x 68   (row=dim,  col=key)   -- transposed
    float* Vs = Kt + 64 * 68;    // 64 x 68   (row=key,  col=dim)
    float* Ps = Vs + 64 * 68;    // 128 x 68  (row=query,col=key)

    const int t  = threadIdx.x;
    const int tx = t & 15, ty = t >> 4;
    const int bh = blockIdx.y;
    const int b  = bh >> 3;
    const int q0 = blockIdx.x * 128;

    const float* qp = Q + (size_t)bh * SEQ * DK;
    const float* kp = K + (size_t)bh * SEQ * DK;
    const float* vp = V + (size_t)bh * SEQ * DK;
    const int*   mp = mask + (size_t)b * SEQ * SEQ;

    // Load Q tile (128 x 64)
    {
        const int r = t & 127, c0 = (t >> 7) * 32;
        #pragma unroll
        for (int ci = 0; ci < 32; ci += 4)
            *(float4*)&Qs[r * 68 + c0 + ci] =
                *(const float4*)&qp[(size_t)(q0 + r) * DK + c0 + ci];
    }

    float2 o[8][2];
    float  m_[8], l_[8];
    #pragma unroll
    for (int i = 0; i < 8; i++) {
        m_[i] = -1e30f; l_[i] = 0.0f;
        o[i][0] = make_float2(0.f, 0.f);
        o[i][1] = make_float2(0.f, 0.f);
    }

    for (int k0 = 0; k0 < SEQ; k0 += 64) {
        __syncthreads();   // previous phase-C reads done
        // Load K transposed + V straight
        {
            const int j = t & 63, e0 = (t >> 6) * 16;
            #pragma unroll
            for (int eq = 0; eq < 16; eq += 4) {
                float4 kv = *(const float4*)&kp[(size_t)(k0 + j) * DK + e0 + eq];
                Kt[(e0 + eq + 0) * 68 + j] = kv.x;
                Kt[(e0 + eq + 1) * 68 + j] = kv.y;
                Kt[(e0 + eq + 2) * 68 + j] = kv.z;
                Kt[(e0 + eq + 3) * 68 + j] = kv.w;
                *(float4*)&Vs[j * 68 + e0 + eq] =
                    *(const float4*)&vp[(size_t)(k0 + j) * DK + e0 + eq];
            }
        }
        __syncthreads();

        // Phase A: S = Q K^T over d=0..63
        float2 s[8][2];
        #pragma unroll
        for (int i = 0; i < 8; i++) {
            s[i][0] = make_float2(0.f, 0.f);
            s[i][1] = make_float2(0.f, 0.f);
        }
        #pragma unroll 8
        for (int e = 0; e < DK; e += 2) {
            float4 ka = *(const float4*)&Kt[(e + 0) * 68 + 4 * tx];
            float4 kb = *(const float4*)&Kt[(e + 1) * 68 + 4 * tx];
            float2 ka0 = make_float2(ka.x, ka.y), ka1 = make_float2(ka.z, ka.w);
            float2 kb0 = make_float2(kb.x, kb.y), kb1 = make_float2(kb.z, kb.w);
            #pragma unroll
            for (int i = 0; i < 8; i++) {
                float2 qd = *(const float2*)&Qs[(ty + 16 * i) * 68 + e];
                float2 a0 = make_float2(qd.x, qd.x);
                float2 a1 = make_float2(qd.y, qd.y);
                s[i][0] = ffma2(a0, ka0, s[i][0]);
                s[i][1] = ffma2(a0, ka1, s[i][1]);
                s[i][0] = ffma2(a1, kb0, s[i][0]);
                s[i][1] = ffma2(a1, kb1, s[i][1]);
            }
        }

        // mask + *8 (faithful quirk) + online softmax
        #pragma unroll
        for (int i = 0; i < 8; i++) {
            const int mrow = q0 + ty + 16 * i;
            const int4 mv = *(const int4*)&mp[(size_t)mrow * SEQ + k0 + 4 * tx];
            float v0 = mv.x ? s[i][0].x * 8.0f : NEGV;
            float v1 = mv.y ? s[i][0].y * 8.0f : NEGV;
            float v2 = mv.z ? s[i][1].x * 8.0f : NEGV;
            float v3 = mv.w ? s[i][1].y * 8.0f : NEGV;

            float mt = fmaxf(fmaxf(v0, v1), fmaxf(v2, v3));
            #pragma unroll
            for (int off = 1; off < 16; off <<= 1)
                mt = fmaxf(mt, __shfl_xor_sync(0xffffffffu, mt, off));
            const float mnew  = fmaxf(m_[i], mt);
            const float scale = __expf(m_[i] - mnew);
            v0 = __expf(v0 - mnew); v1 = __expf(v1 - mnew);
            v2 = __expf(v2 - mnew); v3 = __expf(v3 - mnew);
            float rs = v0 + v1 + v2 + v3;
            #pragma unroll
            for (int off = 1; off < 16; off <<= 1)
                rs += __shfl_xor_sync(0xffffffffu, rs, off);
            l_[i] = l_[i] * scale + rs;
            m_[i] = mnew;
            const float2 sc = make_float2(scale, scale);
            o[i][0] = fmul2(o[i][0], sc);
            o[i][1] = fmul2(o[i][1], sc);

            float4 pv; pv.x = v0; pv.y = v1; pv.z = v2; pv.w = v3;
            *(float4*)&Ps[(ty + 16 * i) * 68 + 4 * tx] = pv;
        }
        __syncthreads();

        // Phase C: O += P @ V over keys e=0..63
        #pragma unroll 8
        for (int e = 0; e < 64; e += 2) {
            float4 va = *(const float4*)&Vs[(e + 0) * 68 + 4 * tx];
            float4 vb = *(const float4*)&Vs[(e + 1) * 68 + 4 * tx];
            float2 va0 = make_float2(va.x, va.y), va1 = make_float2(va.z, va.w);
            float2 vb0 = make_float2(vb.x, vb.y), vb1 = make_float2(vb.z, vb.w);
            #pragma unroll
            for (int i = 0; i < 8; i++) {
                float2 pd = *(const float2*)&Ps[(ty + 16 * i) * 68 + e];
                float2 p0 = make_float2(pd.x, pd.x);
                float2 p1 = make_float2(pd.y, pd.y);
                o[i][0] = ffma2(p0, va0, o[i][0]);
                o[i][1] = ffma2(p0, va1, o[i][1]);
                o[i][0] = ffma2(p1, vb0, o[i][0]);
                o[i][1] = ffma2(p1, vb1, o[i][1]);
            }
        }
    }

    // Epilogue: normalize + store [bh][s][d] (contiguous == reshape quirk)
    float* op = O + (size_t)bh * SEQ * DK;
    #pragma unroll
    for (int i = 0; i < 8; i++) {
        const float inv = 1.0f / l_[i];
        float4 c;
        c.x = o[i][0].x * inv; c.y = o[i][0].y * inv;
        c.z = o[i][1].x * inv; c.w = o[i][1].y * inv;
        *(float4*)&op[(size_t)(q0 + ty + 16 * i) * DK + 4 * tx] = c;
    }
}

extern "C" void kernel_launch(void* const* d_in, const int* in_sizes, int n_in,
                              void* d_out, int out_size)
{
    (void)in_sizes; (void)n_in; (void)out_size;
    const float* query  = (const float*)d_in[0];
    const float* key_in = (const float*)d_in[1];
    const float* value  = (const float*)d_in[2];
    const int*   mask   = (const int*)  d_in[3];
    const float* Wq = (const float*)d_in[4];
    const float* bq = (const float*)d_in[5];
    const float* Wk = (const float*)d_in[6];
    const float* bk = (const float*)d_in[7];
    const float* Wv = (const float*)d_in[8];
    const float* bv = (const float*)d_in[9];
    const float* Wo = (const float*)d_in[10];
    const float* bo = (const float*)d_in[11];
    float* out = (float*)d_out;

    float *qb, *kb, *vb, *ab;
    cudaGetSymbolAddress((void**)&qb, g_q);
    cudaGetSymbolAddress((void**)&kb, g_k);
    cudaGetSymbolAddress((void**)&vb, g_v);
    cudaGetSymbolAddress((void**)&ab, g_att);

    const int attn_smem = (128 + 64 + 64 + 128) * 68 * (int)sizeof(float); // 104448
    cudaFuncSetAttribute(attn_kernel,
                         cudaFuncAttributeMaxDynamicSharedMemorySize, attn_smem);

    dim3 pg(EMB / 128, (NB * SEQ) / 128);   // (4, 64)
    proj_kernel<<<pg, 256>>>(query,  Wq, bq, qb, 1);
    proj_kernel<<<pg, 256>>>(key_in, Wk, bk, kb, 1);
    proj_kernel<<<pg, 256>>>(value,  Wv, bv, vb, 1);

    dim3 ag(SEQ / 128, NB * NH);            // (16, 32)
    attn_kernel<<<ag, 256, attn_smem>>>(qb, kb, vb, mask, ab);

    proj_kernel<<<pg, 256>>>(ab, Wo, bo, out, 0);
}